// round 16
// baseline (speedup 1.0000x reference)
#include <cuda_runtime.h>
#include <cuda_fp16.h>
#include <stdint.h>

#define BATCH        2048
#define IN_DIM       4096
#define OUT_DIM      1024
#define N_EDGES_MAX  16384

#define BT           256    // batch-tile: 256 halves = 512 B per edge row-slice
#define TPB          2      // batch-tiles per block
#define NPB          8      // nodes (warps) per block
#define ECAP         192    // staged-row capacity (Poisson(128) + 5.7 sigma)
#define SECAP        512    // staged edge-meta capacity

// Scratch (no allocations allowed): fp16 transposed x + CSR meta.
__device__ __half g_xt[(size_t)IN_DIM * BATCH];  // 16 MB, x_t[s][b] (L2-resident)
__device__ int    g_offs[OUT_DIM + 1];
__device__ int2   g_edges[N_EDGES_MAX];          // (src, weight_bits)

// ---------------- Fused transpose(+fp16 convert) + prologue ----------------
__global__ __launch_bounds__(256)
void transpose_prologue_kernel(const float* __restrict__ x,
                               const int* __restrict__ edge_src,
                               const float* __restrict__ weights,
                               const int* __restrict__ edge_dst,
                               int n_edges) {
    const int tid = threadIdx.y * 32 + threadIdx.x;
    const int tx = threadIdx.x, ty = threadIdx.y;

    if (blockIdx.y == 0 && blockIdx.x < 64) {
        const int i = blockIdx.x * 256 + tid;
        if (i < n_edges) {
            g_edges[i] = make_int2(edge_src[i], __float_as_int(weights[i]));
            const int d  = edge_dst[i];
            const int dp = (i == 0) ? -1 : edge_dst[i - 1];
            for (int o = dp + 1; o <= d; o++) g_offs[o] = i;
            if (i == n_edges - 1)
                for (int o = d + 1; o <= OUT_DIM; o++) g_offs[o] = n_edges;
        }
    }

    __shared__ float tile[32][33];
    const int c0 = blockIdx.x * 32;
    const int b0 = blockIdx.y * 32;
    #pragma unroll
    for (int i = 0; i < 4; i++)
        tile[ty + i * 8][tx] = x[(size_t)(b0 + ty + i * 8) * IN_DIM + c0 + tx];
    __syncthreads();
    {
        const int c_local = tid >> 3;
        const int g       = (tid & 7) * 4;
        __half h[4];
        #pragma unroll
        for (int k = 0; k < 4; k++)
            h[k] = __float2half(tile[g + k][c_local]);
        *reinterpret_cast<uint2*>(&g_xt[(size_t)(c0 + c_local) * BATCH + b0 + g])
            = *reinterpret_cast<uint2*>(h);
    }
}

// ---------------- async-copy helpers ----------------
__device__ __forceinline__ uint32_t s2u(const void* p) {
    return (uint32_t)__cvta_generic_to_shared(p);
}
__device__ __forceinline__ void mbar_init(uint32_t mbar, uint32_t cnt) {
    asm volatile("mbarrier.init.shared.b64 [%0], %1;"
                 :: "r"(mbar), "r"(cnt) : "memory");
}
__device__ __forceinline__ void mbar_expect_tx(uint32_t mbar, uint32_t bytes) {
    asm volatile("mbarrier.arrive.expect_tx.shared.b64 _, [%0], %1;"
                 :: "r"(mbar), "r"(bytes) : "memory");
}
__device__ __forceinline__ void mbar_wait(uint32_t mbar, uint32_t parity) {
    asm volatile(
        "{\n\t.reg .pred P;\n\t"
        "WAIT_%=:\n\t"
        "mbarrier.try_wait.parity.acquire.cta.shared::cta.b64 P, [%0], %1, 0x989680;\n\t"
        "@!P bra WAIT_%=;\n\t}"
        :: "r"(mbar), "r"(parity) : "memory");
}
__device__ __forceinline__ void bulk_g2s(uint32_t dst, const void* src,
                                         uint32_t bytes, uint32_t mbar) {
    asm volatile(
        "cp.async.bulk.shared::cluster.global.mbarrier::complete_tx::bytes "
        "[%0], [%1], %2, [%3];"
        :: "r"(dst), "l"(src), "r"(bytes), "r"(mbar) : "memory");
}

// ---------------- Gather: bulk-staged rows, smem consume ----------------
__device__ __forceinline__ float act(float v) {
    float e  = __expf(2.0f * v);
    float th = 1.0f - __fdividef(2.0f, e + 1.0f);
    return __fdividef(1.0f, 1.0f + __expf(-th));
}
__device__ __forceinline__ void acc_h2(float4 v, __half2 w2, __half2* a) {
    const __half2* h = reinterpret_cast<const __half2*>(&v);
    #pragma unroll
    for (int j = 0; j < 4; j++) a[j] = __hfma2(h[j], w2, a[j]);
}

extern __shared__ char g_buf[];   // ECAP * 512 bytes staged rows

__global__ __launch_bounds__(NPB * 32)
void gather_kernel(float* __restrict__ out) {
    __shared__ int2  se[SECAP];
    __shared__ float t[BT][NPB + 1];
    __shared__ alignas(8) uint64_t mbar_s;

    const int tid  = threadIdx.x;
    const int warp = tid >> 5;
    const int lane = tid & 31;
    const int o    = blockIdx.y * NPB + warp;          // node (warp-uniform)

    const uint32_t mbar = s2u(&mbar_s);
    const uint32_t bufa = s2u(g_buf);

    // ---- Block edge range ----
    const int e_lo = g_offs[blockIdx.y * NPB];
    const int e_hi = g_offs[blockIdx.y * NPB + NPB];
    const int tot  = e_hi - e_lo;

    if (tid == 0) mbar_init(mbar, 1);
    if (tot <= SECAP)
        for (int i = tid; i < tot; i += NPB * 32)
            se[i] = __ldg(&g_edges[e_lo + i]);
    __syncthreads();

    const int beg = g_offs[o];
    const int end = g_offs[o + 1];
    const int jbeg = beg - e_lo, jend = end - e_lo;    // local edge indices

    const bool staged = (tot <= ECAP);

    for (int tile = 0; tile < TPB; tile++) {
        const int bt = blockIdx.x * TPB + tile;        // batch-tile index
        const int bq = bt * 32 + lane;                 // float4 idx in x_t row

        __half2 a[4];
        #pragma unroll
        for (int j = 0; j < 4; j++) a[j] = __half2half2(__ushort_as_half(0));

        if (staged) {
            // ---- Stage phase: one 512-B bulk copy per edge ----
            if (tot > 0) {
                if (tid == 0) mbar_expect_tx(mbar, (uint32_t)tot * 512u);
                __syncthreads();   // expect visible; prev-phase buf consumed
                if (tid < tot) {
                    const __half* src = g_xt + (size_t)se[tid].x * BATCH
                                             + (size_t)bt * BT;
                    bulk_g2s(bufa + (uint32_t)tid * 512u, src, 512u, mbar);
                }
                mbar_wait(mbar, tile & 1);
            }
            // ---- Consume: conflict-free LDS.128 + HFMA2 ----
            const float4* b4 = reinterpret_cast<const float4*>(g_buf);
            int j = jbeg;
            for (; j + 3 < jend; j += 4) {
                int2 p0 = se[j + 0];  int2 p1 = se[j + 1];
                int2 p2 = se[j + 2];  int2 p3 = se[j + 3];
                float4 v0 = b4[(j + 0) * 32 + lane];
                float4 v1 = b4[(j + 1) * 32 + lane];
                float4 v2 = b4[(j + 2) * 32 + lane];
                float4 v3 = b4[(j + 3) * 32 + lane];
                acc_h2(v0, __float2half2_rn(__int_as_float(p0.y)), a);
                acc_h2(v1, __float2half2_rn(__int_as_float(p1.y)), a);
                acc_h2(v2, __float2half2_rn(__int_as_float(p2.y)), a);
                acc_h2(v3, __float2half2_rn(__int_as_float(p3.y)), a);
            }
            for (; j < jend; j++) {
                int2 p = se[j];
                acc_h2(b4[j * 32 + lane],
                       __float2half2_rn(__int_as_float(p.y)), a);
            }
        } else {
            // ---- Fallback (tot > ECAP, statistically ~never): direct LDG ----
            const int2* ebase = (tot <= SECAP) ? (const int2*)se - e_lo
                                               : (const int2*)g_edges;
            const float4* xt4 = reinterpret_cast<const float4*>(g_xt);
            int e = beg;
            for (; e + 3 < end; e += 4) {
                int2 p0 = ebase[e + 0];  int2 p1 = ebase[e + 1];
                int2 p2 = ebase[e + 2];  int2 p3 = ebase[e + 3];
                float4 v0 = xt4[(size_t)p0.x * (BATCH / 8) + bq];
                float4 v1 = xt4[(size_t)p1.x * (BATCH / 8) + bq];
                float4 v2 = xt4[(size_t)p2.x * (BATCH / 8) + bq];
                float4 v3 = xt4[(size_t)p3.x * (BATCH / 8) + bq];
                acc_h2(v0, __float2half2_rn(__int_as_float(p0.y)), a);
                acc_h2(v1, __float2half2_rn(__int_as_float(p1.y)), a);
                acc_h2(v2, __float2half2_rn(__int_as_float(p2.y)), a);
                acc_h2(v3, __float2half2_rn(__int_as_float(p3.y)), a);
            }
            for (; e < end; e++) {
                int2 p = ebase[e];
                acc_h2(xt4[(size_t)p.x * (BATCH / 8) + bq],
                       __float2half2_rn(__int_as_float(p.y)), a);
            }
        }

        // ---- Activations ----
        float f[8];
        #pragma unroll
        for (int j = 0; j < 4; j++) {
            float2 fv = __half22float2(a[j]);
            f[2 * j + 0] = act(fv.x);
            f[2 * j + 1] = act(fv.y);
        }

        // ---- smem transpose + coalesced stores ----
        __syncthreads();
        {
            const int b = lane * 8;
            #pragma unroll
            for (int j = 0; j < 8; j++) t[b + j][warp] = f[j];
        }
        __syncthreads();
        {
            const int i = tid;                     // 0..255
            const int b = bt * BT + i;
            float4 s0v = make_float4(t[i][0], t[i][1], t[i][2], t[i][3]);
            float4 s1v = make_float4(t[i][4], t[i][5], t[i][6], t[i][7]);
            float4* dst = reinterpret_cast<float4*>(out + (size_t)b * OUT_DIM
                                                    + blockIdx.y * NPB);
            dst[0] = s0v;
            dst[1] = s1v;
        }
    }
}

extern "C" void kernel_launch(void* const* d_in, const int* in_sizes, int n_in,
                              void* d_out, int out_size) {
    const float* x        = (const float*)d_in[0];   // [2048, 4096] f32
    const float* weights  = (const float*)d_in[1];   // [16384] f32
    const int*   edge_src = (const int*)d_in[2];     // [16384] i32
    const int*   edge_dst = (const int*)d_in[3];     // [16384] i32 (sorted)
    float*       out      = (float*)d_out;           // [2048, 1024] f32

    const int n_edges = in_sizes[1];
    const int dyn_smem = ECAP * 512;                 // 96 KB staged rows

    static bool attr_set = false;
    if (!attr_set) {
        cudaFuncSetAttribute(gather_kernel,
                             cudaFuncAttributeMaxDynamicSharedMemorySize,
                             dyn_smem);
        attr_set = true;
    }

    // 1) Fused transpose+fp16-convert + CSR-meta build
    transpose_prologue_kernel<<<dim3(IN_DIM / 32, BATCH / 32), dim3(32, 8)>>>(
        x, edge_src, weights, edge_dst, n_edges);

    // 2) Gather: 512 blocks, 2/SM (96 KB buf), bulk-copy staging pipeline
    gather_kernel<<<dim3(BATCH / (BT * TPB), OUT_DIM / NPB), NPB * 32,
                    dyn_smem>>>(out);
}

// round 17
// speedup vs baseline: 1.0755x; 1.0755x over previous
#include <cuda_runtime.h>
#include <cuda_fp16.h>
#include <stdint.h>

#define BATCH        2048
#define IN_DIM       4096
#define OUT_DIM      1024
#define N_EDGES_MAX  16384

#define BT           256    // gather batch-tile (8 halves per lane per LDG.128)
#define TPB          2      // batch-tiles per gather block
#define NPB          8      // nodes (warps) per gather block
#define EDGE_CAP     512    // smem edge staging capacity (guarded)

#define TM           64     // transpose: IN cols per tile
#define TBB          64     // transpose: batch rows per tile

// Scratch (no allocations allowed): fp16 transposed x + CSR meta.
__device__ __half g_xt[(size_t)IN_DIM * BATCH];  // 16 MB, x_t[s][b] (L2-resident)
__device__ int    g_offs[OUT_DIM + 1];
__device__ int2   g_edges[N_EDGES_MAX];          // (src, weight_bits)

// ---------------- Fused transpose(+fp16 convert) + prologue ----------------
// 64x64 tiles: fp16 write side emits 128 B contiguous per 4 lanes -> full
// sectors (the 32-wide version wrote 64 B half-sectors, doubling effective
// DRAM write traffic).
__global__ __launch_bounds__(256)
void transpose_prologue_kernel(const float* __restrict__ x,
                               const int* __restrict__ edge_src,
                               const float* __restrict__ weights,
                               const int* __restrict__ edge_dst,
                               int n_edges) {
    const int tid = threadIdx.x;

    // ---- Embedded prologue (first 64 blocks of row y==0) ----
    if (blockIdx.y == 0 && blockIdx.x < 64) {
        const int i = blockIdx.x * 256 + tid;
        if (i < n_edges) {
            g_edges[i] = make_int2(edge_src[i], __float_as_int(weights[i]));
            const int d  = edge_dst[i];
            const int dp = (i == 0) ? -1 : edge_dst[i - 1];
            for (int o = dp + 1; o <= d; o++) g_offs[o] = i;
            if (i == n_edges - 1)
                for (int o = d + 1; o <= OUT_DIM; o++) g_offs[o] = n_edges;
        }
    }

    __shared__ float tile[TBB][TM + 1];   // [batch][col], pad 65
    const int c0 = blockIdx.x * TM;
    const int b0 = blockIdx.y * TBB;

    // ---- Load: thread t handles batch row r = t>>2, quarter q = t&3 ----
    {
        const int r = tid >> 2, q = tid & 3;
        const float4* src = reinterpret_cast<const float4*>(
            x + (size_t)(b0 + r) * IN_DIM + c0) + q * 4;
        #pragma unroll
        for (int k = 0; k < 4; k++) {
            float4 v = src[k];
            const int c = q * 16 + k * 4;
            tile[r][c + 0] = v.x;
            tile[r][c + 1] = v.y;
            tile[r][c + 2] = v.z;
            tile[r][c + 3] = v.w;
        }
    }
    __syncthreads();

    // ---- Store: thread t -> column c_local = t>>2, batch seg (t&3)*16.
    // 16 halves = 32 B per thread, 128 B contiguous per 4-lane group. ----
    {
        const int c_local = tid >> 2;
        const int g       = (tid & 3) * 16;
        __half h[16];
        #pragma unroll
        for (int k = 0; k < 16; k++)
            h[k] = __float2half(tile[g + k][c_local]);
        uint4* dst = reinterpret_cast<uint4*>(
            &g_xt[(size_t)(c0 + c_local) * BATCH + b0 + g]);
        dst[0] = *reinterpret_cast<uint4*>(h);
        dst[1] = *reinterpret_cast<uint4*>(h + 8);
    }
}

// ---------------- Gather: R14 verbatim (measured best: 17.28 us) ----------
__device__ __forceinline__ float act(float v) {
    float e  = __expf(2.0f * v);
    float th = 1.0f - __fdividef(2.0f, e + 1.0f);
    return __fdividef(1.0f, 1.0f + __expf(-th));
}

// acc[0..3] (half2) += v (4x half2) * w2 (splat) -- 4 HFMA2 per edge.
__device__ __forceinline__ void acc_h2(float4 v, __half2 w2, __half2* a) {
    const __half2* h = reinterpret_cast<const __half2*>(&v);
    #pragma unroll
    for (int j = 0; j < 4; j++) a[j] = __hfma2(h[j], w2, a[j]);
}

__global__ __launch_bounds__(NPB * 32, 4)   // <=64 regs, 4 blocks/SM, 1 wave
void gather_kernel(float* __restrict__ out) {
    __shared__ int2  se[EDGE_CAP];
    __shared__ float t[BT][NPB + 1];

    const int warp = threadIdx.x >> 5;
    const int lane = threadIdx.x & 31;
    const int o    = blockIdx.y * NPB + warp;          // node (warp-uniform)

    const float4* __restrict__ xt4 = reinterpret_cast<const float4*>(g_xt);

    // ---- Stage this block's contiguous edge range once (reused by tiles) ----
    const int e_lo = g_offs[blockIdx.y * NPB];
    const int e_hi = g_offs[blockIdx.y * NPB + NPB];
    const int tot  = e_hi - e_lo;
    const int2* ebase;
    if (tot <= EDGE_CAP) {
        for (int i = threadIdx.x; i < tot; i += NPB * 32)
            se[i] = __ldg(&g_edges[e_lo + i]);
        ebase = se - e_lo;                     // index by global edge id
    } else {
        ebase = g_edges;                       // gmem fallback
    }
    __syncthreads();

    const int beg = g_offs[o];
    const int end = g_offs[o + 1];

    for (int tile = 0; tile < TPB; tile++) {
        const int bt = blockIdx.x * TPB + tile;        // batch-tile index
        const int bq = bt * 32 + lane;                 // float4 index in row

        __half2 a[4];
        #pragma unroll
        for (int j = 0; j < 4; j++) a[j] = __half2half2(__ushort_as_half(0));

        // Edge loop: broadcast LDS edge reads, 8 independent LDG.128 in flight.
        int e = beg;
        for (; e + 7 < end; e += 8) {
            int2 p0 = ebase[e + 0];  int2 p1 = ebase[e + 1];
            int2 p2 = ebase[e + 2];  int2 p3 = ebase[e + 3];
            int2 p4 = ebase[e + 4];  int2 p5 = ebase[e + 5];
            int2 p6 = ebase[e + 6];  int2 p7 = ebase[e + 7];
            float4 v0 = xt4[(size_t)p0.x * (BATCH / 8) + bq];
            float4 v1 = xt4[(size_t)p1.x * (BATCH / 8) + bq];
            float4 v2 = xt4[(size_t)p2.x * (BATCH / 8) + bq];
            float4 v3 = xt4[(size_t)p3.x * (BATCH / 8) + bq];
            float4 v4 = xt4[(size_t)p4.x * (BATCH / 8) + bq];
            float4 v5 = xt4[(size_t)p5.x * (BATCH / 8) + bq];
            float4 v6 = xt4[(size_t)p6.x * (BATCH / 8) + bq];
            float4 v7 = xt4[(size_t)p7.x * (BATCH / 8) + bq];
            acc_h2(v0, __float2half2_rn(__int_as_float(p0.y)), a);
            acc_h2(v1, __float2half2_rn(__int_as_float(p1.y)), a);
            acc_h2(v2, __float2half2_rn(__int_as_float(p2.y)), a);
            acc_h2(v3, __float2half2_rn(__int_as_float(p3.y)), a);
            acc_h2(v4, __float2half2_rn(__int_as_float(p4.y)), a);
            acc_h2(v5, __float2half2_rn(__int_as_float(p5.y)), a);
            acc_h2(v6, __float2half2_rn(__int_as_float(p6.y)), a);
            acc_h2(v7, __float2half2_rn(__int_as_float(p7.y)), a);
        }
        for (; e < end; e++) {
            int2 p = ebase[e];
            acc_h2(xt4[(size_t)p.x * (BATCH / 8) + bq],
                   __float2half2_rn(__int_as_float(p.y)), a);
        }

        // Activations (fp32 epilogue)
        float f[8];
        #pragma unroll
        for (int j = 0; j < 4; j++) {
            float2 fv = __half22float2(a[j]);
            f[2 * j + 0] = act(fv.x);
            f[2 * j + 1] = act(fv.y);
        }

        // smem transpose for coalesced stores
        __syncthreads();                        // protects se (tile 0) / t
        {
            const int b = lane * 8;
            #pragma unroll
            for (int j = 0; j < 8; j++) t[b + j][warp] = f[j];
        }
        __syncthreads();

        // Thread i stores batch row (bt*BT + i): 8 contiguous floats
        {
            const int i = threadIdx.x;             // 0..255
            const int b = bt * BT + i;
            float4 s0v = make_float4(t[i][0], t[i][1], t[i][2], t[i][3]);
            float4 s1v = make_float4(t[i][4], t[i][5], t[i][6], t[i][7]);
            float4* dst = reinterpret_cast<float4*>(out + (size_t)b * OUT_DIM
                                                    + blockIdx.y * NPB);
            dst[0] = s0v;
            dst[1] = s1v;
        }
    }
}

extern "C" void kernel_launch(void* const* d_in, const int* in_sizes, int n_in,
                              void* d_out, int out_size) {
    const float* x        = (const float*)d_in[0];   // [2048, 4096] f32
    const float* weights  = (const float*)d_in[1];   // [16384] f32
    const int*   edge_src = (const int*)d_in[2];     // [16384] i32
    const int*   edge_dst = (const int*)d_in[3];     // [16384] i32 (sorted)
    float*       out      = (float*)d_out;           // [2048, 1024] f32

    const int n_edges = in_sizes[1];

    // 1) Fused 64x64 transpose+fp16-convert + CSR-meta build
    transpose_prologue_kernel<<<dim3(IN_DIM / TM, BATCH / TBB), 256>>>(
        x, edge_src, weights, edge_dst, n_edges);

    // 2) Gather: 512 blocks (2 batch-tiles each), 4 blocks/SM, single wave
    gather_kernel<<<dim3(BATCH / (BT * TPB), OUT_DIM / NPB), NPB * 32>>>(out);
}